// round 4
// baseline (speedup 1.0000x reference)
#include <cuda_runtime.h>
#include <cstdint>
#include <cstddef>

#define TDIM 512
#define BDIM 128
#define EDIM 128
#define SDIM 1024
#define NLEV 10
#define PBSTRIDE (NLEV * TDIM)
#define NCH 16
#define CHT 32
#define INFV 3.0e38f

typedef unsigned long long ull;

// ---------------- device scratch ----------------
__device__ float g_cTB[TDIM * BDIM];        // [t][b] u - TP
__device__ float g_t0T[BDIM * TDIM];        // [b][tau]  (gemm layout)
__device__ float g_TPT[BDIM * TDIM];        // [b][tau]
__device__ float g_t0TB[TDIM * BDIM];       // [tau][b]  (k_m layout)
__device__ float g_TPTB[TDIM * BDIM];       // [tau][b]
__device__ float g_P[BDIM * PBSTRIDE];      // [b][k][tau] sparse min table
__device__ float g_Pt[NLEV * TDIM * BDIM];  // [k][tau][b] transposed table
__device__ float g_m[SDIM * TDIM];          // [j][t]
__device__ float g_A[NCH * BDIM];
__device__ float g_B[NCH * BDIM];
__device__ float g_Ls[NCH * BDIM];

// ---------------- packed f32x2 helpers ----------------
__device__ __forceinline__ ull ffma2(ull a, ull b, ull c) {
    ull d;
    asm("fma.rn.f32x2 %0, %1, %2, %3;" : "=l"(d) : "l"(a), "l"(b), "l"(c));
    return d;
}
__device__ __forceinline__ ull pack2(float x) {
    ull d;
    asm("mov.b64 %0, {%1, %2};" : "=l"(d) : "f"(x), "f"(x));
    return d;
}
__device__ __forceinline__ void unpack2(ull v, float& lo, float& hi) {
    asm("mov.b64 {%0, %1}, %2;" : "=f"(lo), "=f"(hi) : "l"(v));
}

// ---------------- K1a: per-chunk scan composition ----------------
__global__ void k_lev1(const float* __restrict__ d1, const float* __restrict__ d2,
                       const float* __restrict__ u) {
    int c = blockIdx.x, b = threadIdx.x;
    float A = 0.f, Bv = 0.f;
    int t0 = c * CHT;
#pragma unroll 4
    for (int t = t0; t < t0 + CHT; ++t) {
        float x = d1[t * BDIM + b] + d2[t * BDIM + b] - u[t * BDIM + b];
        A += x;
        Bv = fmaxf(Bv + x, 0.f);
    }
    g_A[c * BDIM + b] = A;
    g_B[c * BDIM + b] = Bv;
}

__global__ void k_lev2() {
    int b = threadIdx.x;
    float L = 0.f;
#pragma unroll
    for (int c = 0; c < NCH; ++c) {
        g_Ls[c * BDIM + b] = L;
        L = fmaxf(L + g_A[c * BDIM + b], g_B[c * BDIM + b]);
    }
}

// ---------------- K1c: emit all per-batch arrays (dual layouts) ----------
__global__ void k_lev3(const float* __restrict__ d1, const float* __restrict__ d2,
                       const float* __restrict__ u) {
    int c = blockIdx.x, b = threadIdx.x;
    float L = g_Ls[c * BDIM + b];
    int t0 = c * CHT;
#pragma unroll 4
    for (int t = t0; t < t0 + CHT; ++t) {
        float a1 = d1[t * BDIM + b];
        float a2 = d2[t * BDIM + b];
        float uu = u[t * BDIM + b];
        float top0 = L + a1;
        float TP = top0 + a2;
        g_t0T[b * TDIM + t] = top0;
        g_TPT[b * TDIM + t] = TP;
        g_t0TB[t * BDIM + b] = top0;
        g_TPTB[t * BDIM + b] = TP;
        g_cTB[t * BDIM + b] = uu - TP;
        L = fmaxf(TP - uu, 0.f);
        g_P[b * PBSTRIDE + t] = L;          // level 0, [b][tau]
        g_Pt[t * BDIM + b] = L;             // level 0, [tau][b]
    }
}

// ---------------- K2: sparse table levels 1..9, both layouts -------------
__global__ __launch_bounds__(256) void k_table() {
    int b = blockIdx.x, tid = threadIdx.x;
    __shared__ float s0[TDIM], s1[TDIM];
    float* base = g_P + b * PBSTRIDE;
    s0[tid] = base[tid];
    s0[tid + 256] = base[tid + 256];
    __syncthreads();
    float* cur = s0;
    float* nxt = s1;
    for (int k = 1; k < NLEV; ++k) {
        int h = 1 << (k - 1);
#pragma unroll
        for (int i = 0; i < 2; ++i) {
            int tau = tid + i * 256;
            float v = cur[tau];
            if (tau + h < TDIM) v = fminf(v, cur[tau + h]);
            nxt[tau] = v;
            base[k * TDIM + tau] = v;
            g_Pt[((size_t)k * TDIM + tau) * BDIM + b] = v;
        }
        __syncthreads();
        float* tmp = cur; cur = nxt; nxt = tmp;
    }
}

// ---------------- K3: m[t][j] = max_b (c + C_j), float4 over b ----------
__global__ __launch_bounds__(256) void k_m() {
    int t = blockIdx.x, tid = threadIdx.x;
    const float* cc = g_cTB + (size_t)t * BDIM;

    for (int tau = tid; tau <= t; tau += 256) {
        int n = t - tau;
        float me = -INFV, mo = -INFV;
        const float* a0 = g_t0TB + (size_t)tau * BDIM;
        const float* p0 = g_TPTB + (size_t)tau * BDIM;
        if (n) {
            int k = 31 - __clz(n);
            const float* r1 = g_Pt + ((size_t)k * TDIM + tau) * BDIM;
            const float* r2 = g_Pt + ((size_t)k * TDIM + (t - (1 << k))) * BDIM;
#pragma unroll 4
            for (int b4 = 0; b4 < BDIM; b4 += 4) {
                float4 A = *(const float4*)(a0 + b4);
                float4 P = *(const float4*)(p0 + b4);
                float4 C = *(const float4*)(cc + b4);
                float4 X = *(const float4*)(r1 + b4);
                float4 Y = *(const float4*)(r2 + b4);
                float Rx = fminf(X.x, Y.x), Ry = fminf(X.y, Y.y);
                float Rz = fminf(X.z, Y.z), Rw = fminf(X.w, Y.w);
                me = fmaxf(me, fmaxf(fmaxf(C.x + fminf(A.x, Rx), C.y + fminf(A.y, Ry)),
                                     fmaxf(C.z + fminf(A.z, Rz), C.w + fminf(A.w, Rw))));
                mo = fmaxf(mo, fmaxf(fmaxf(C.x + fminf(P.x, Rx), C.y + fminf(P.y, Ry)),
                                     fmaxf(C.z + fminf(P.z, Rz), C.w + fminf(P.w, Rw))));
            }
        } else {
#pragma unroll 4
            for (int b4 = 0; b4 < BDIM; b4 += 4) {
                float4 A = *(const float4*)(a0 + b4);
                float4 P = *(const float4*)(p0 + b4);
                float4 C = *(const float4*)(cc + b4);
                me = fmaxf(me, fmaxf(fmaxf(C.x + A.x, C.y + A.y),
                                     fmaxf(C.z + A.z, C.w + A.w)));
                mo = fmaxf(mo, fmaxf(fmaxf(C.x + P.x, C.y + P.y),
                                     fmaxf(C.z + P.z, C.w + P.w)));
            }
        }
        g_m[(size_t)(2 * tau) * TDIM + t] = me;
        g_m[(size_t)(2 * tau + 1) * TDIM + t] = mo;
    }
}

// ---------------- K4: tiled GEMM, 64-row t-tiles, packed weights ---------
// CTA = (64 t-rows) x (batch b). 256 threads: 4 rows x 8 cols each.
__global__ __launch_bounds__(256, 2) void k_gemm(const float* __restrict__ v1,
                                                 const float* __restrict__ v2,
                                                 float* __restrict__ out) {
    int tile = 7 - blockIdx.x;  // heavy tiles first
    int b = blockIdx.y;
    int t0 = tile * 64;
    int tid = threadIdx.x;
    int rg = tid >> 4, cg = tid & 15;
    int r0 = rg * 4, e0 = cg * 8;

    __shared__ float sv1[8][EDIM];
    __shared__ float sv2[8][EDIM];
    __shared__ ull sw[8][64][2];  // [s][t][we|wo], packed broadcast pairs

    ull acc[4][4];
#pragma unroll
    for (int i = 0; i < 4; ++i)
#pragma unroll
        for (int j = 0; j < 4; ++j) acc[i][j] = 0ull;

    const float* Pb = g_P + b * PBSTRIDE;
    int tl = tid & 63, sp = tid >> 6;  // weight phase: 2 s per thread
    int tmy = t0 + tl;
    int ls = tid >> 5, le = (tid & 31) * 4;  // staging: thread -> (s row, e chunk)

    int nst = (tile + 1) * 8;

    float4 rv1, rv2;
    {
        size_t base = ((size_t)ls * BDIM + b) * EDIM + le;
        rv1 = *(const float4*)(v1 + base);
        rv2 = *(const float4*)(v2 + base);
    }

    for (int st = 0; st < nst; ++st) {
        __syncthreads();
        *(float4*)&sv1[ls][le] = rv1;
        *(float4*)&sv2[ls][le] = rv2;

        // weights for s = sp*2, sp*2+1
#pragma unroll
        for (int ss = 0; ss < 2; ++ss) {
            int s = sp * 2 + ss;
            int tau = st * 8 + s;
            float we = 0.f, wo = 0.f;
            if (tau <= tmy) {
                float a0 = g_t0T[b * TDIM + tau];
                float p0 = g_TPT[b * TDIM + tau];
                int n = tmy - tau;
                float R;
                if (n) {
                    int k = 31 - __clz(n);
                    R = fminf(Pb[k * TDIM + tau], Pb[k * TDIM + tmy - (1 << k)]);
                } else {
                    R = INFV;
                }
                float Ca = fminf(a0, R);
                float Cp = fminf(p0, R);
                float mo = g_m[(size_t)(2 * tau + 1) * TDIM + tmy];
                float me = g_m[(size_t)(2 * tau) * TDIM + tmy];
                wo = fminf(Cp - Ca, mo);
                float Cm1 = 0.f;
                if (tau) {
                    Cm1 = fminf(g_TPT[b * TDIM + tau - 1], fminf(Pb[tau - 1], R));
                }
                we = fminf(Ca - Cm1, me);
            }
            sw[s][tl][0] = pack2(we);
            sw[s][tl][1] = pack2(wo);
        }
        __syncthreads();

        // prefetch next stage
        if (st + 1 < nst) {
            int tau = (st + 1) * 8 + ls;
            size_t base = ((size_t)tau * BDIM + b) * EDIM + le;
            rv1 = *(const float4*)(v1 + base);
            rv2 = *(const float4*)(v2 + base);
        }

        // FMA phase
#pragma unroll
        for (int s = 0; s < 8; ++s) {
            ulonglong2 a0v = *(const ulonglong2*)&sv1[s][e0];
            ulonglong2 a1v = *(const ulonglong2*)&sv1[s][e0 + 4];
            ulonglong2 b0v = *(const ulonglong2*)&sv2[s][e0];
            ulonglong2 b1v = *(const ulonglong2*)&sv2[s][e0 + 4];
            ull va[4] = {a0v.x, a0v.y, a1v.x, a1v.y};
            ull vb[4] = {b0v.x, b0v.y, b1v.x, b1v.y};
#pragma unroll
            for (int i = 0; i < 4; ++i) {
                ulonglong2 wp = *(const ulonglong2*)&sw[s][r0 + i][0];
#pragma unroll
                for (int j = 0; j < 4; ++j) {
                    acc[i][j] = ffma2(wp.x, va[j], ffma2(wp.y, vb[j], acc[i][j]));
                }
            }
        }
    }

    // write out [T][B][E]
#pragma unroll
    for (int i = 0; i < 4; ++i) {
        float r[8];
#pragma unroll
        for (int j = 0; j < 4; ++j) unpack2(acc[i][j], r[2 * j], r[2 * j + 1]);
        size_t basei = ((size_t)(t0 + r0 + i) * BDIM + b) * EDIM + e0;
        *reinterpret_cast<float4*>(out + basei) = make_float4(r[0], r[1], r[2], r[3]);
        *reinterpret_cast<float4*>(out + basei + 4) = make_float4(r[4], r[5], r[6], r[7]);
    }
}

extern "C" void kernel_launch(void* const* d_in, const int* in_sizes, int n_in,
                              void* d_out, int out_size) {
    const float* v1 = (const float*)d_in[0];
    const float* v2 = (const float*)d_in[1];
    const float* d1 = (const float*)d_in[2];
    const float* d2 = (const float*)d_in[3];
    const float* u  = (const float*)d_in[4];
    float* out = (float*)d_out;

    k_lev1<<<NCH, BDIM>>>(d1, d2, u);
    k_lev2<<<1, BDIM>>>();
    k_lev3<<<NCH, BDIM>>>(d1, d2, u);
    k_table<<<BDIM, 256>>>();
    k_m<<<TDIM, 256>>>();
    dim3 grid(8, BDIM);
    k_gemm<<<grid, 256>>>(v1, v2, out);
}

// round 7
// speedup vs baseline: 1.1448x; 1.1448x over previous
#include <cuda_runtime.h>
#include <cstdint>
#include <cstddef>

#define TDIM 512
#define BDIM 128
#define EDIM 128
#define SDIM 1024
#define NLEV 10
#define PBSTRIDE (NLEV * TDIM)
#define NCH 16
#define CHT 32
#define INFV 3.0e38f

typedef unsigned long long ull;

// ---------------- device scratch ----------------
__device__ float g_cTB[TDIM * BDIM];        // [t][b] u - TP
__device__ float g_t0T[BDIM * TDIM];        // [b][tau]
__device__ float g_TPT[BDIM * TDIM];        // [b][tau]
__device__ float g_t0TB[TDIM * BDIM];       // [tau][b]
__device__ float g_TPTB[TDIM * BDIM];       // [tau][b]
__device__ float g_P[BDIM * PBSTRIDE];      // [b][k][tau] sparse min table
__device__ float g_Pt[NLEV * TDIM * BDIM];  // [k][tau][b]
__device__ float g_m[SDIM * TDIM];          // [j][t] scalar m
__device__ ull   g_mp[SDIM * TDIM];         // [j][t] packed (m,m)
__device__ int   g_js[TDIM];                // first j with m>0
__device__ float g_A[NCH * BDIM];
__device__ float g_B[NCH * BDIM];
__device__ float g_Ls[NCH * BDIM];

// ---------------- packed f32x2 helpers ----------------
__device__ __forceinline__ ull ffma2(ull a, ull b, ull c) {
    ull d;
    asm("fma.rn.f32x2 %0, %1, %2, %3;" : "=l"(d) : "l"(a), "l"(b), "l"(c));
    return d;
}
__device__ __forceinline__ ull pack2(float x) {
    ull d;
    asm("mov.b64 %0, {%1, %2};" : "=l"(d) : "f"(x), "f"(x));
    return d;
}
__device__ __forceinline__ void unpack2(ull v, float& lo, float& hi) {
    asm("mov.b64 {%0, %1}, %2;" : "=f"(lo), "=f"(hi) : "l"(v));
}

// ---------------- K0: zero m arrays ----------------
__global__ void k_zero() {
    size_t i = (size_t)blockIdx.x * blockDim.x + threadIdx.x;
    size_t n = (size_t)SDIM * TDIM;
    for (; i < n; i += (size_t)gridDim.x * blockDim.x) {
        g_m[i] = 0.f;
        g_mp[i] = 0ull;
    }
}

// ---------------- K1: level scan ----------------
__global__ void k_lev1(const float* __restrict__ d1, const float* __restrict__ d2,
                       const float* __restrict__ u) {
    int c = blockIdx.x, b = threadIdx.x;
    float A = 0.f, Bv = 0.f;
    int t0 = c * CHT;
#pragma unroll 4
    for (int t = t0; t < t0 + CHT; ++t) {
        float x = d1[t * BDIM + b] + d2[t * BDIM + b] - u[t * BDIM + b];
        A += x;
        Bv = fmaxf(Bv + x, 0.f);
    }
    g_A[c * BDIM + b] = A;
    g_B[c * BDIM + b] = Bv;
}

__global__ void k_lev2() {
    int b = threadIdx.x;
    float L = 0.f;
#pragma unroll
    for (int c = 0; c < NCH; ++c) {
        g_Ls[c * BDIM + b] = L;
        L = fmaxf(L + g_A[c * BDIM + b], g_B[c * BDIM + b]);
    }
}

__global__ void k_lev3(const float* __restrict__ d1, const float* __restrict__ d2,
                       const float* __restrict__ u) {
    int c = blockIdx.x, b = threadIdx.x;
    float L = g_Ls[c * BDIM + b];
    int t0 = c * CHT;
#pragma unroll 4
    for (int t = t0; t < t0 + CHT; ++t) {
        float a1 = d1[t * BDIM + b];
        float a2 = d2[t * BDIM + b];
        float uu = u[t * BDIM + b];
        float top0 = L + a1;
        float TP = top0 + a2;
        g_t0T[b * TDIM + t] = top0;
        g_TPT[b * TDIM + t] = TP;
        g_t0TB[t * BDIM + b] = top0;
        g_TPTB[t * BDIM + b] = TP;
        g_cTB[t * BDIM + b] = uu - TP;
        L = fmaxf(TP - uu, 0.f);
        g_P[b * PBSTRIDE + t] = L;
        g_Pt[t * BDIM + b] = L;
    }
}

// ---------------- K2: sparse min table ----------------
__global__ __launch_bounds__(256) void k_table() {
    int b = blockIdx.x, tid = threadIdx.x;
    __shared__ float s0[TDIM], s1[TDIM];
    float* base = g_P + b * PBSTRIDE;
    s0[tid] = base[tid];
    s0[tid + 256] = base[tid + 256];
    __syncthreads();
    float* cur = s0;
    float* nxt = s1;
    for (int k = 1; k < NLEV; ++k) {
        int h = 1 << (k - 1);
#pragma unroll
        for (int i = 0; i < 2; ++i) {
            int tau = tid + i * 256;
            float v = cur[tau];
            if (tau + h < TDIM) v = fminf(v, cur[tau + h]);
            nxt[tau] = v;
            base[k * TDIM + tau] = v;
            g_Pt[((size_t)k * TDIM + tau) * BDIM + b] = v;
        }
        __syncthreads();
        float* tmp = cur; cur = nxt; nxt = tmp;
    }
}

// ---------------- K3: m[t][j] = max_b (c + C_j) ----------------
__global__ __launch_bounds__(256) void k_m() {
    int t = blockIdx.x, tid = threadIdx.x;
    const float* cc = g_cTB + (size_t)t * BDIM;

    for (int tau = tid; tau <= t; tau += 256) {
        int n = t - tau;
        float me = -INFV, mo = -INFV;
        const float* a0 = g_t0TB + (size_t)tau * BDIM;
        const float* p0 = g_TPTB + (size_t)tau * BDIM;
        if (n) {
            int k = 31 - __clz(n);
            const float* r1 = g_Pt + ((size_t)k * TDIM + tau) * BDIM;
            const float* r2 = g_Pt + ((size_t)k * TDIM + (t - (1 << k))) * BDIM;
#pragma unroll 4
            for (int b4 = 0; b4 < BDIM; b4 += 4) {
                float4 A = *(const float4*)(a0 + b4);
                float4 P = *(const float4*)(p0 + b4);
                float4 C = *(const float4*)(cc + b4);
                float4 X = *(const float4*)(r1 + b4);
                float4 Y = *(const float4*)(r2 + b4);
                float Rx = fminf(X.x, Y.x), Ry = fminf(X.y, Y.y);
                float Rz = fminf(X.z, Y.z), Rw = fminf(X.w, Y.w);
                me = fmaxf(me, fmaxf(fmaxf(C.x + fminf(A.x, Rx), C.y + fminf(A.y, Ry)),
                                     fmaxf(C.z + fminf(A.z, Rz), C.w + fminf(A.w, Rw))));
                mo = fmaxf(mo, fmaxf(fmaxf(C.x + fminf(P.x, Rx), C.y + fminf(P.y, Ry)),
                                     fmaxf(C.z + fminf(P.z, Rz), C.w + fminf(P.w, Rw))));
            }
        } else {
#pragma unroll 4
            for (int b4 = 0; b4 < BDIM; b4 += 4) {
                float4 A = *(const float4*)(a0 + b4);
                float4 P = *(const float4*)(p0 + b4);
                float4 C = *(const float4*)(cc + b4);
                me = fmaxf(me, fmaxf(fmaxf(C.x + A.x, C.y + A.y),
                                     fmaxf(C.z + A.z, C.w + A.w)));
                mo = fmaxf(mo, fmaxf(fmaxf(C.x + P.x, C.y + P.y),
                                     fmaxf(C.z + P.z, C.w + P.w)));
            }
        }
        g_m[(size_t)(2 * tau) * TDIM + t] = me;
        g_m[(size_t)(2 * tau + 1) * TDIM + t] = mo;
        g_mp[(size_t)(2 * tau) * TDIM + t] = pack2(me);
        g_mp[(size_t)(2 * tau + 1) * TDIM + t] = pack2(mo);
    }
}

// ---------------- K3b: j*(t) = first j with m[t][j] > 0 (m monotone) -----
__global__ void k_jstar() {
    int t = blockIdx.x * blockDim.x + threadIdx.x;
    if (t >= TDIM) return;
    int lo = 0, hi = 2 * t + 2;
    while (lo < hi) {
        int mid = (lo + hi) >> 1;
        if (g_m[(size_t)mid * TDIM + t] > 0.f) hi = mid;
        else lo = mid + 1;
    }
    g_js[t] = lo;
}

// ---------------- K4: pure GEMM out1[t,(b,e)] = sum_j m[t,j] V[j,b,e] ----
// CTA = (128 t-rows tile) x (batch b). 256 threads: 8 rows x 8 cols.
__global__ __launch_bounds__(256, 2) void k_gemm(const float* __restrict__ v1,
                                                 const float* __restrict__ v2,
                                                 float* __restrict__ out) {
    int b = blockIdx.x;
    int tile = 3 - blockIdx.y;  // heavy tiles first
    int t0 = tile * 128;
    int tid = threadIdx.x;
    int rg = tid >> 4, cg = tid & 15;
    int r0 = rg * 8, e0 = cg * 8;

    __shared__ float sV[2][16][EDIM];   // 16 j-rows of values (v1/v2 interleaved)
    __shared__ ull sMp[2][16][128];     // packed m pairs per (j, t-row)

    ull acc[8][4];
#pragma unroll
    for (int i = 0; i < 8; ++i)
#pragma unroll
        for (int j = 0; j < 4; ++j) acc[i][j] = 0ull;

    int nst = 16 * (tile + 1);

    // staging thread mapping
    int vs = tid >> 5, ve = (tid & 31) * 4;        // values: 2 rounds
    int ws = tid >> 6, wt = (tid & 63) * 2;        // weights: 4 rounds

    float4 rv[2];
    ulonglong2 rw[4];

    auto load_stage = [&](int st) {
        int j0 = st * 16;
#pragma unroll
        for (int k = 0; k < 2; ++k) {
            int s = vs + k * 8;
            int j = j0 + s;
            int tau = j >> 1;
            const float* src = (j & 1) ? v2 : v1;
            rv[k] = *(const float4*)&src[((size_t)tau * BDIM + b) * EDIM + ve];
        }
#pragma unroll
        for (int k = 0; k < 4; ++k) {
            int s = ws + k * 4;
            rw[k] = *(const ulonglong2*)&g_mp[(size_t)(j0 + s) * TDIM + t0 + wt];
        }
    };
    auto store_stage = [&](int bf) {
#pragma unroll
        for (int k = 0; k < 2; ++k)
            *(float4*)&sV[bf][vs + k * 8][ve] = rv[k];
#pragma unroll
        for (int k = 0; k < 4; ++k)
            *(ulonglong2*)&sMp[bf][ws + k * 4][wt] = rw[k];
    };

    load_stage(0);
    for (int st = 0; st < nst; ++st) {
        int bf = st & 1;
        store_stage(bf);
        if (st + 1 < nst) load_stage(st + 1);
        __syncthreads();
#pragma unroll
        for (int s = 0; s < 16; ++s) {
            ulonglong2 w01 = *(const ulonglong2*)&sMp[bf][s][r0];
            ulonglong2 w23 = *(const ulonglong2*)&sMp[bf][s][r0 + 2];
            ulonglong2 w45 = *(const ulonglong2*)&sMp[bf][s][r0 + 4];
            ulonglong2 w67 = *(const ulonglong2*)&sMp[bf][s][r0 + 6];
            ulonglong2 vv0 = *(const ulonglong2*)&sV[bf][s][e0];
            ulonglong2 vv1 = *(const ulonglong2*)&sV[bf][s][e0 + 4];
            ull va[4] = {vv0.x, vv0.y, vv1.x, vv1.y};
            ull w[8] = {w01.x, w01.y, w23.x, w23.y, w45.x, w45.y, w67.x, w67.y};
#pragma unroll
            for (int i = 0; i < 8; ++i)
#pragma unroll
                for (int j = 0; j < 4; ++j)
                    acc[i][j] = ffma2(w[i], va[j], acc[i][j]);
        }
        __syncthreads();
    }

    // write out [T][B][E]
#pragma unroll
    for (int i = 0; i < 8; ++i) {
        float r[8];
#pragma unroll
        for (int j = 0; j < 4; ++j) unpack2(acc[i][j], r[2 * j], r[2 * j + 1]);
        size_t basei = ((size_t)(t0 + r0 + i) * BDIM + b) * EDIM + e0;
        *reinterpret_cast<float4*>(out + basei) = make_float4(r[0], r[1], r[2], r[3]);
        *reinterpret_cast<float4*>(out + basei + 4) = make_float4(r[4], r[5], r[6], r[7]);
    }
}

// ---------------- K5: banded correction: out -= relu(m - s_b) * V -------
// CTA per t; 8 warps; warp handles batches b = w, w+8, ...; lanes over e.
__global__ __launch_bounds__(256) void k_corr(const float* __restrict__ v1,
                                              const float* __restrict__ v2,
                                              float* __restrict__ out) {
    int t = blockIdx.x;
    int w = threadIdx.x >> 5, lane = threadIdx.x & 31;
    int js = g_js[t];
    if (js >= 2 * t + 2) return;
    int tau0 = js >> 1;

    for (int b = w; b < BDIM; b += 8) {
        const float* Pb = g_P + b * PBSTRIDE;
        const float* t0b = g_t0T + b * TDIM;
        const float* tpb = g_TPT + b * TDIM;
        float4* op = (float4*)out + ((size_t)t * BDIM + b) * 32 + lane;
        float4 o = *op;
        bool touched = false;

        for (int tau = tau0; tau <= t; ++tau) {
            int n = t - tau;
            float R;
            if (n) {
                int k = 31 - __clz(n);
                R = fminf(Pb[k * TDIM + tau], Pb[k * TDIM + t - (1 << k)]);
            } else {
                R = INFV;
            }
            float Ca = fminf(t0b[tau], R);
            float Cp = fminf(tpb[tau], R);
            float Cm1 = tau ? fminf(tpb[tau - 1], fminf(Pb[tau - 1], R)) : 0.f;
            float s0 = Ca - Cm1;
            float s1 = Cp - Ca;
            float m0 = g_m[(size_t)(2 * tau) * TDIM + t];
            float m1 = g_m[(size_t)(2 * tau + 1) * TDIM + t];
            float c0 = fmaxf(m0 - s0, 0.f);
            float c1 = fmaxf(m1 - s1, 0.f);
            if (c0 > 0.f || c1 > 0.f) {
                size_t vb = ((size_t)tau * BDIM + b) * EDIM + lane * 4;
                float4 a = *(const float4*)(v1 + vb);
                float4 p = *(const float4*)(v2 + vb);
                o.x -= c0 * a.x + c1 * p.x;
                o.y -= c0 * a.y + c1 * p.y;
                o.z -= c0 * a.z + c1 * p.z;
                o.w -= c0 * a.w + c1 * p.w;
                touched = true;
            }
        }
        if (touched) *op = o;
    }
}

extern "C" void kernel_launch(void* const* d_in, const int* in_sizes, int n_in,
                              void* d_out, int out_size) {
    const float* v1 = (const float*)d_in[0];
    const float* v2 = (const float*)d_in[1];
    const float* d1 = (const float*)d_in[2];
    const float* d2 = (const float*)d_in[3];
    const float* u  = (const float*)d_in[4];
    float* out = (float*)d_out;

    k_zero<<<512, 256>>>();
    k_lev1<<<NCH, BDIM>>>(d1, d2, u);
    k_lev2<<<1, BDIM>>>();
    k_lev3<<<NCH, BDIM>>>(d1, d2, u);
    k_table<<<BDIM, 256>>>();
    k_m<<<TDIM, 256>>>();
    k_jstar<<<2, 256>>>();
    dim3 grid(BDIM, 4);
    k_gemm<<<grid, 256>>>(v1, v2, out);
    k_corr<<<TDIM, 256>>>(v1, v2, out);
}

// round 8
// speedup vs baseline: 1.2125x; 1.0592x over previous
#include <cuda_runtime.h>
#include <cstdint>
#include <cstddef>

#define TDIM 512
#define BDIM 128
#define EDIM 128
#define SDIM 1024
#define NLEV 10
#define PBSTRIDE (NLEV * TDIM)
#define NCH 16
#define CHT 32
#define INFV 3.0e38f

typedef unsigned long long ull;

// ---------------- device scratch ----------------
__device__ float g_cTB[TDIM * BDIM];        // [t][b] u - TP
__device__ float g_t0T[BDIM * TDIM];        // [b][tau]  (corr layout)
__device__ float g_TPT[BDIM * TDIM];        // [b][tau]
__device__ float g_t0TB[TDIM * BDIM];       // [tau][b]  (k_m layout)
__device__ float g_TPTB[TDIM * BDIM];       // [tau][b]
__device__ float g_P[BDIM * PBSTRIDE];      // [b][k][tau] sparse min table
__device__ float g_Pt[NLEV * TDIM * BDIM];  // [k][tau][b]
__device__ float g_m[SDIM * TDIM];          // [j][t] scalar m
__device__ ull   g_mp[SDIM * TDIM];         // [j][t] packed (m,m)
__device__ int   g_js[TDIM];                // first j with m>0
__device__ float g_A[NCH * BDIM];
__device__ float g_B[NCH * BDIM];
__device__ float g_Ls[NCH * BDIM];

// ---------------- packed f32x2 helpers ----------------
__device__ __forceinline__ ull ffma2(ull a, ull b, ull c) {
    ull d;
    asm("fma.rn.f32x2 %0, %1, %2, %3;" : "=l"(d) : "l"(a), "l"(b), "l"(c));
    return d;
}
__device__ __forceinline__ ull pack2(float x) {
    ull d;
    asm("mov.b64 %0, {%1, %2};" : "=l"(d) : "f"(x), "f"(x));
    return d;
}
__device__ __forceinline__ void unpack2(ull v, float& lo, float& hi) {
    asm("mov.b64 {%0, %1}, %2;" : "=f"(lo), "=f"(hi) : "l"(v));
}

// ---------------- K1: level scan chunk composition + g_mp zeroing --------
__global__ __launch_bounds__(256) void k_zl1(const float* __restrict__ d1,
                                             const float* __restrict__ d2,
                                             const float* __restrict__ u) {
    int c = blockIdx.x, tid = threadIdx.x;
    if (tid < BDIM) {
        int b = tid;
        float A = 0.f, Bv = 0.f;
        int t0 = c * CHT;
#pragma unroll 4
        for (int t = t0; t < t0 + CHT; ++t) {
            float x = d1[t * BDIM + b] + d2[t * BDIM + b] - u[t * BDIM + b];
            A += x;
            Bv = fmaxf(Bv + x, 0.f);
        }
        g_A[c * BDIM + b] = A;
        g_B[c * BDIM + b] = Bv;
    } else {
        // zero g_mp (the only array gemm reads beyond what k_m writes)
        int z = c * 128 + (tid - 128);  // 0..2047
        ulonglong2* p = (ulonglong2*)g_mp;
        const int n = SDIM * TDIM / 2;
        ulonglong2 zz; zz.x = 0ull; zz.y = 0ull;
        for (int i = z; i < n; i += NCH * 128) p[i] = zz;
    }
}

__global__ void k_lev2() {
    int b = threadIdx.x;
    float L = 0.f;
#pragma unroll
    for (int c = 0; c < NCH; ++c) {
        g_Ls[c * BDIM + b] = L;
        L = fmaxf(L + g_A[c * BDIM + b], g_B[c * BDIM + b]);
    }
}

// ---------------- K1c: emit per-batch arrays, coalesced layouts only -----
__global__ void k_lev3(const float* __restrict__ d1, const float* __restrict__ d2,
                       const float* __restrict__ u) {
    int c = blockIdx.x, b = threadIdx.x;
    float L = g_Ls[c * BDIM + b];
    int t0 = c * CHT;
#pragma unroll 4
    for (int t = t0; t < t0 + CHT; ++t) {
        float a1 = d1[t * BDIM + b];
        float a2 = d2[t * BDIM + b];
        float uu = u[t * BDIM + b];
        float top0 = L + a1;
        float TP = top0 + a2;
        g_t0TB[t * BDIM + b] = top0;
        g_TPTB[t * BDIM + b] = TP;
        g_cTB[t * BDIM + b] = uu - TP;
        L = fmaxf(TP - uu, 0.f);
        g_Pt[t * BDIM + b] = L;  // level 0, [tau][b]
    }
}

// ---------------- K2: transpose + sparse min table -----------------------
__global__ __launch_bounds__(256) void k_table() {
    int b = blockIdx.x, tid = threadIdx.x;
    __shared__ float s0[TDIM], s1[TDIM];
    float* base = g_P + b * PBSTRIDE;

    // transpose loads (stride-BDIM gathers, MLP-hidden)
#pragma unroll
    for (int i = 0; i < 2; ++i) {
        int t = tid + i * 256;
        float lv = g_Pt[(size_t)t * BDIM + b];
        s0[t] = lv;
        base[t] = lv;
        g_t0T[b * TDIM + t] = g_t0TB[(size_t)t * BDIM + b];
        g_TPT[b * TDIM + t] = g_TPTB[(size_t)t * BDIM + b];
    }
    __syncthreads();
    float* cur = s0;
    float* nxt = s1;
    for (int k = 1; k < NLEV; ++k) {
        int h = 1 << (k - 1);
#pragma unroll
        for (int i = 0; i < 2; ++i) {
            int tau = tid + i * 256;
            float v = cur[tau];
            if (tau + h < TDIM) v = fminf(v, cur[tau + h]);
            nxt[tau] = v;
            base[k * TDIM + tau] = v;
            g_Pt[((size_t)k * TDIM + tau) * BDIM + b] = v;
        }
        __syncthreads();
        float* tmp = cur; cur = nxt; nxt = tmp;
    }
}

// ---------------- K3: m[t][j] = max_b (c + C_j)  (+ fused j* search) -----
__global__ __launch_bounds__(256) void k_m() {
    int t = blockIdx.x, tid = threadIdx.x;
    const float* cc = g_cTB + (size_t)t * BDIM;
    __shared__ int sjs;
    if (tid == 0) sjs = 2 * t + 2;
    __syncthreads();

    for (int tau = tid; tau <= t; tau += 256) {
        int n = t - tau;
        float me = -INFV, mo = -INFV;
        const float* a0 = g_t0TB + (size_t)tau * BDIM;
        const float* p0 = g_TPTB + (size_t)tau * BDIM;
        if (n) {
            int k = 31 - __clz(n);
            const float* r1 = g_Pt + ((size_t)k * TDIM + tau) * BDIM;
            const float* r2 = g_Pt + ((size_t)k * TDIM + (t - (1 << k))) * BDIM;
#pragma unroll 4
            for (int b4 = 0; b4 < BDIM; b4 += 4) {
                float4 A = *(const float4*)(a0 + b4);
                float4 P = *(const float4*)(p0 + b4);
                float4 C = *(const float4*)(cc + b4);
                float4 X = *(const float4*)(r1 + b4);
                float4 Y = *(const float4*)(r2 + b4);
                float Rx = fminf(X.x, Y.x), Ry = fminf(X.y, Y.y);
                float Rz = fminf(X.z, Y.z), Rw = fminf(X.w, Y.w);
                me = fmaxf(me, fmaxf(fmaxf(C.x + fminf(A.x, Rx), C.y + fminf(A.y, Ry)),
                                     fmaxf(C.z + fminf(A.z, Rz), C.w + fminf(A.w, Rw))));
                mo = fmaxf(mo, fmaxf(fmaxf(C.x + fminf(P.x, Rx), C.y + fminf(P.y, Ry)),
                                     fmaxf(C.z + fminf(P.z, Rz), C.w + fminf(P.w, Rw))));
            }
        } else {
#pragma unroll 4
            for (int b4 = 0; b4 < BDIM; b4 += 4) {
                float4 A = *(const float4*)(a0 + b4);
                float4 P = *(const float4*)(p0 + b4);
                float4 C = *(const float4*)(cc + b4);
                me = fmaxf(me, fmaxf(fmaxf(C.x + A.x, C.y + A.y),
                                     fmaxf(C.z + A.z, C.w + A.w)));
                mo = fmaxf(mo, fmaxf(fmaxf(C.x + P.x, C.y + P.y),
                                     fmaxf(C.z + P.z, C.w + P.w)));
            }
        }
        g_m[(size_t)(2 * tau) * TDIM + t] = me;
        g_m[(size_t)(2 * tau + 1) * TDIM + t] = mo;
        g_mp[(size_t)(2 * tau) * TDIM + t] = pack2(me);
        g_mp[(size_t)(2 * tau + 1) * TDIM + t] = pack2(mo);
        // j* candidate (m monotone in j => min positive j is the cutoff)
        if (me > 0.f) atomicMin(&sjs, 2 * tau);
        else if (mo > 0.f) atomicMin(&sjs, 2 * tau + 1);
    }
    __syncthreads();
    if (tid == 0) g_js[t] = sjs;
}

// ---------------- K4: pure GEMM out1[t,(b,e)] = sum_j m[t,j] V[j,b,e] ----
// CTA = (128 t-rows tile) x (batch b). 256 threads: 8 rows x 8 cols.
__global__ __launch_bounds__(256, 2) void k_gemm(const float* __restrict__ v1,
                                                 const float* __restrict__ v2,
                                                 float* __restrict__ out) {
    int b = blockIdx.x;
    int tile = 3 - blockIdx.y;  // heavy tiles first
    int t0 = tile * 128;
    int tid = threadIdx.x;
    int rg = tid >> 4, cg = tid & 15;
    int r0 = rg * 8, e0 = cg * 8;

    __shared__ float sV[2][16][EDIM];
    __shared__ ull sMp[2][16][128];

    ull acc[8][4];
#pragma unroll
    for (int i = 0; i < 8; ++i)
#pragma unroll
        for (int j = 0; j < 4; ++j) acc[i][j] = 0ull;

    int nst = 16 * (tile + 1);

    int vs = tid >> 5, ve = (tid & 31) * 4;
    int ws = tid >> 6, wt = (tid & 63) * 2;

    float4 rv[2];
    ulonglong2 rw[4];

    auto load_stage = [&](int st) {
        int j0 = st * 16;
#pragma unroll
        for (int k = 0; k < 2; ++k) {
            int s = vs + k * 8;
            int j = j0 + s;
            int tau = j >> 1;
            const float* src = (j & 1) ? v2 : v1;
            rv[k] = *(const float4*)&src[((size_t)tau * BDIM + b) * EDIM + ve];
        }
#pragma unroll
        for (int k = 0; k < 4; ++k) {
            int s = ws + k * 4;
            rw[k] = *(const ulonglong2*)&g_mp[(size_t)(j0 + s) * TDIM + t0 + wt];
        }
    };
    auto store_stage = [&](int bf) {
#pragma unroll
        for (int k = 0; k < 2; ++k)
            *(float4*)&sV[bf][vs + k * 8][ve] = rv[k];
#pragma unroll
        for (int k = 0; k < 4; ++k)
            *(ulonglong2*)&sMp[bf][ws + k * 4][wt] = rw[k];
    };

    load_stage(0);
    for (int st = 0; st < nst; ++st) {
        int bf = st & 1;
        store_stage(bf);
        if (st + 1 < nst) load_stage(st + 1);
        __syncthreads();
#pragma unroll
        for (int s = 0; s < 16; ++s) {
            ulonglong2 vv0 = *(const ulonglong2*)&sV[bf][s][e0];
            ulonglong2 vv1 = *(const ulonglong2*)&sV[bf][s][e0 + 4];
            ull va0 = vv0.x, va1 = vv0.y, va2 = vv1.x, va3 = vv1.y;
#pragma unroll
            for (int h = 0; h < 4; ++h) {
                ulonglong2 wp = *(const ulonglong2*)&sMp[bf][s][r0 + 2 * h];
                acc[2 * h][0] = ffma2(wp.x, va0, acc[2 * h][0]);
                acc[2 * h][1] = ffma2(wp.x, va1, acc[2 * h][1]);
                acc[2 * h][2] = ffma2(wp.x, va2, acc[2 * h][2]);
                acc[2 * h][3] = ffma2(wp.x, va3, acc[2 * h][3]);
                acc[2 * h + 1][0] = ffma2(wp.y, va0, acc[2 * h + 1][0]);
                acc[2 * h + 1][1] = ffma2(wp.y, va1, acc[2 * h + 1][1]);
                acc[2 * h + 1][2] = ffma2(wp.y, va2, acc[2 * h + 1][2]);
                acc[2 * h + 1][3] = ffma2(wp.y, va3, acc[2 * h + 1][3]);
            }
        }
        __syncthreads();
    }

    // write out [T][B][E]
#pragma unroll
    for (int i = 0; i < 8; ++i) {
        float r[8];
#pragma unroll
        for (int j = 0; j < 4; ++j) unpack2(acc[i][j], r[2 * j], r[2 * j + 1]);
        size_t basei = ((size_t)(t0 + r0 + i) * BDIM + b) * EDIM + e0;
        *reinterpret_cast<float4*>(out + basei) = make_float4(r[0], r[1], r[2], r[3]);
        *reinterpret_cast<float4*>(out + basei + 4) = make_float4(r[4], r[5], r[6], r[7]);
    }
}

// ---------------- K5: banded correction: out -= relu(m - s_b) * V -------
__global__ __launch_bounds__(256) void k_corr(const float* __restrict__ v1,
                                              const float* __restrict__ v2,
                                              float* __restrict__ out) {
    int t = blockIdx.x;
    int w = threadIdx.x >> 5, lane = threadIdx.x & 31;
    int js = g_js[t];
    if (js >= 2 * t + 2) return;
    int tau0 = js >> 1;

    for (int b = w; b < BDIM; b += 8) {
        const float* Pb = g_P + b * PBSTRIDE;
        const float* t0b = g_t0T + b * TDIM;
        const float* tpb = g_TPT + b * TDIM;
        float4* op = (float4*)out + ((size_t)t * BDIM + b) * 32 + lane;
        float4 o = *op;
        bool touched = false;

        for (int tau = tau0; tau <= t; ++tau) {
            int n = t - tau;
            float R;
            if (n) {
                int k = 31 - __clz(n);
                R = fminf(Pb[k * TDIM + tau], Pb[k * TDIM + t - (1 << k)]);
            } else {
                R = INFV;
            }
            float Ca = fminf(t0b[tau], R);
            float Cp = fminf(tpb[tau], R);
            float Cm1 = tau ? fminf(tpb[tau - 1], fminf(Pb[tau - 1], R)) : 0.f;
            float s0 = Ca - Cm1;
            float s1 = Cp - Ca;
            float m0 = g_m[(size_t)(2 * tau) * TDIM + t];
            float m1 = g_m[(size_t)(2 * tau + 1) * TDIM + t];
            float c0 = fmaxf(m0 - s0, 0.f);
            float c1 = fmaxf(m1 - s1, 0.f);
            if (c0 > 0.f || c1 > 0.f) {
                size_t vb = ((size_t)tau * BDIM + b) * EDIM + lane * 4;
                float4 a = *(const float4*)(v1 + vb);
                float4 p = *(const float4*)(v2 + vb);
                o.x -= c0 * a.x + c1 * p.x;
                o.y -= c0 * a.y + c1 * p.y;
                o.z -= c0 * a.z + c1 * p.z;
                o.w -= c0 * a.w + c1 * p.w;
                touched = true;
            }
        }
        if (touched) *op = o;
    }
}

extern "C" void kernel_launch(void* const* d_in, const int* in_sizes, int n_in,
                              void* d_out, int out_size) {
    const float* v1 = (const float*)d_in[0];
    const float* v2 = (const float*)d_in[1];
    const float* d1 = (const float*)d_in[2];
    const float* d2 = (const float*)d_in[3];
    const float* u  = (const float*)d_in[4];
    float* out = (float*)d_out;

    k_zl1<<<NCH, 256>>>(d1, d2, u);     // launch 1
    k_lev2<<<1, BDIM>>>();              // launch 2
    k_lev3<<<NCH, BDIM>>>(d1, d2, u);   // launch 3
    k_table<<<BDIM, 256>>>();           // launch 4
    k_m<<<TDIM, 256>>>();               // launch 5
    dim3 grid(BDIM, 4);
    k_gemm<<<grid, 256>>>(v1, v2, out); // launch 6 (ncu skip-5 window)
    k_corr<<<TDIM, 256>>>(v1, v2, out); // launch 7
}

// round 10
// speedup vs baseline: 1.2147x; 1.0018x over previous
#include <cuda_runtime.h>
#include <cstdint>
#include <cstddef>

#define TDIM 512
#define BDIM 128
#define EDIM 128
#define SDIM 1024
#define NLEV 10
#define PBSTRIDE (NLEV * TDIM)
#define NCH 16
#define CHT 32
#define INFV 3.0e38f

typedef unsigned long long ull;

// ---------------- device scratch ----------------
__device__ float g_cTB[TDIM * BDIM];        // [t][b] u - TP
__device__ float g_t0T[BDIM * TDIM];        // [b][tau]  (corr layout)
__device__ float g_TPT[BDIM * TDIM];        // [b][tau]
__device__ float g_t0TB[TDIM * BDIM];       // [tau][b]  (k_m layout)
__device__ float g_TPTB[TDIM * BDIM];       // [tau][b]
__device__ float g_P[BDIM * PBSTRIDE];      // [b][k][tau] sparse min table
__device__ float g_Pt[NLEV * TDIM * BDIM];  // [k][tau][b]
__device__ float g_m[SDIM * TDIM];          // [j][t] scalar m
__device__ ull   g_mp[SDIM * TDIM];         // [j][t] packed (m,m)
__device__ int   g_js[TDIM];                // first j with m>0
__device__ float g_A[NCH * BDIM];
__device__ float g_B[NCH * BDIM];

// ---------------- packed f32x2 helpers ----------------
__device__ __forceinline__ ull ffma2(ull a, ull b, ull c) {
    ull d;
    asm("fma.rn.f32x2 %0, %1, %2, %3;" : "=l"(d) : "l"(a), "l"(b), "l"(c));
    return d;
}
__device__ __forceinline__ ull pack2(float x) {
    ull d;
    asm("mov.b64 %0, {%1, %2};" : "=l"(d) : "f"(x), "f"(x));
    return d;
}
__device__ __forceinline__ void unpack2(ull v, float& lo, float& hi) {
    asm("mov.b64 {%0, %1}, %2;" : "=f"(lo), "=f"(hi) : "l"(v));
}

// ---------------- K_A: per-chunk scan composition + g_mp zeroing ---------
__global__ __launch_bounds__(256) void k_A(const float* __restrict__ d1,
                                           const float* __restrict__ d2,
                                           const float* __restrict__ u) {
    int c = blockIdx.x, tid = threadIdx.x;
    if (tid < BDIM) {
        int b = tid;
        float A = 0.f, Bv = 0.f;
        int t0 = c * CHT;
#pragma unroll 4
        for (int t = t0; t < t0 + CHT; ++t) {
            float x = d1[t * BDIM + b] + d2[t * BDIM + b] - u[t * BDIM + b];
            A += x;
            Bv = fmaxf(Bv + x, 0.f);
        }
        g_A[c * BDIM + b] = A;
        g_B[c * BDIM + b] = Bv;
    } else {
        int z = c * 128 + (tid - 128);  // 0..2047
        ulonglong2* p = (ulonglong2*)g_mp;
        const int n = SDIM * TDIM / 2;
        ulonglong2 zz; zz.x = 0ull; zz.y = 0ull;
        for (int i = z; i < n; i += NCH * 128) p[i] = zz;
    }
}

// ---------------- K_B: fused prefix-compose + walk + emit + sparse table -
// One CTA per batch b; 256 threads.
__global__ __launch_bounds__(256) void k_B(const float* __restrict__ d1,
                                           const float* __restrict__ d2,
                                           const float* __restrict__ u) {
    int b = blockIdx.x, tid = threadIdx.x;
    __shared__ float s0[TDIM], s1[TDIM];

    if (tid < NCH) {
        // compose prefix of chunk states 0..tid-1
        float L = 0.f;
        for (int k = 0; k < tid; ++k)
            L = fmaxf(L + g_A[k * BDIM + b], g_B[k * BDIM + b]);
        int t0 = tid * CHT;
        float* t0Trow = g_t0T + (size_t)b * TDIM;
        float* TPTrow = g_TPT + (size_t)b * TDIM;
        float* Prow = g_P + (size_t)b * PBSTRIDE;
#pragma unroll 4
        for (int t = t0; t < t0 + CHT; ++t) {
            float a1 = d1[t * BDIM + b];
            float a2 = d2[t * BDIM + b];
            float uu = u[t * BDIM + b];
            float top0 = L + a1;
            float TP = top0 + a2;
            g_t0TB[t * BDIM + b] = top0;
            g_TPTB[t * BDIM + b] = TP;
            g_cTB[t * BDIM + b] = uu - TP;
            t0Trow[t] = top0;
            TPTrow[t] = TP;
            L = fmaxf(TP - uu, 0.f);
            s0[t] = L;
            Prow[t] = L;
            g_Pt[(size_t)t * BDIM + b] = L;
        }
    }
    __syncthreads();

    // sparse table levels 1..9
    float* base = g_P + (size_t)b * PBSTRIDE;
    float* cur = s0;
    float* nxt = s1;
    for (int k = 1; k < NLEV; ++k) {
        int h = 1 << (k - 1);
#pragma unroll
        for (int i = 0; i < 2; ++i) {
            int tau = tid + i * 256;
            float v = cur[tau];
            if (tau + h < TDIM) v = fminf(v, cur[tau + h]);
            nxt[tau] = v;
            base[k * TDIM + tau] = v;
            g_Pt[((size_t)k * TDIM + tau) * BDIM + b] = v;
        }
        __syncthreads();
        float* tmp = cur; cur = nxt; nxt = tmp;
    }
}

// ---------------- K3: m[t][j] = max_b (c + C_j)  (+ fused j* search) -----
__global__ __launch_bounds__(256) void k_m() {
    int t = blockIdx.x, tid = threadIdx.x;
    const float* cc = g_cTB + (size_t)t * BDIM;
    __shared__ int sjs;
    if (tid == 0) sjs = 2 * t + 2;
    __syncthreads();

    for (int tau = tid; tau <= t; tau += 256) {
        int n = t - tau;
        float me = -INFV, mo = -INFV;
        const float* a0 = g_t0TB + (size_t)tau * BDIM;
        const float* p0 = g_TPTB + (size_t)tau * BDIM;
        if (n) {
            int k = 31 - __clz(n);
            const float* r1 = g_Pt + ((size_t)k * TDIM + tau) * BDIM;
            const float* r2 = g_Pt + ((size_t)k * TDIM + (t - (1 << k))) * BDIM;
#pragma unroll 4
            for (int b4 = 0; b4 < BDIM; b4 += 4) {
                float4 A = *(const float4*)(a0 + b4);
                float4 P = *(const float4*)(p0 + b4);
                float4 C = *(const float4*)(cc + b4);
                float4 X = *(const float4*)(r1 + b4);
                float4 Y = *(const float4*)(r2 + b4);
                float Rx = fminf(X.x, Y.x), Ry = fminf(X.y, Y.y);
                float Rz = fminf(X.z, Y.z), Rw = fminf(X.w, Y.w);
                me = fmaxf(me, fmaxf(fmaxf(C.x + fminf(A.x, Rx), C.y + fminf(A.y, Ry)),
                                     fmaxf(C.z + fminf(A.z, Rz), C.w + fminf(A.w, Rw))));
                mo = fmaxf(mo, fmaxf(fmaxf(C.x + fminf(P.x, Rx), C.y + fminf(P.y, Ry)),
                                     fmaxf(C.z + fminf(P.z, Rz), C.w + fminf(P.w, Rw))));
            }
        } else {
#pragma unroll 4
            for (int b4 = 0; b4 < BDIM; b4 += 4) {
                float4 A = *(const float4*)(a0 + b4);
                float4 P = *(const float4*)(p0 + b4);
                float4 C = *(const float4*)(cc + b4);
                me = fmaxf(me, fmaxf(fmaxf(C.x + A.x, C.y + A.y),
                                     fmaxf(C.z + A.z, C.w + A.w)));
                mo = fmaxf(mo, fmaxf(fmaxf(C.x + P.x, C.y + P.y),
                                     fmaxf(C.z + P.z, C.w + P.w)));
            }
        }
        g_m[(size_t)(2 * tau) * TDIM + t] = me;
        g_m[(size_t)(2 * tau + 1) * TDIM + t] = mo;
        g_mp[(size_t)(2 * tau) * TDIM + t] = pack2(me);
        g_mp[(size_t)(2 * tau + 1) * TDIM + t] = pack2(mo);
        if (me > 0.f) atomicMin(&sjs, 2 * tau);
        else if (mo > 0.f) atomicMin(&sjs, 2 * tau + 1);
    }
    __syncthreads();
    if (tid == 0) g_js[t] = sjs;
}

// ---------------- K4: pure GEMM out1[t,(b,e)] = sum_j m[t,j] V[j,b,e] ----
// CTA = (128 t-rows tile) x (batch b). 256 threads: 8 rows x 8 cols.
// Double-buffered smem, ONE __syncthreads per stage.
__global__ __launch_bounds__(256, 2) void k_gemm(const float* __restrict__ v1,
                                                 const float* __restrict__ v2,
                                                 float* __restrict__ out) {
    int b = blockIdx.x;
    int tile = 3 - blockIdx.y;  // heavy tiles first
    int t0 = tile * 128;
    int tid = threadIdx.x;
    int rg = tid >> 4, cg = tid & 15;
    int r0 = rg * 8, e0 = cg * 8;

    __shared__ float sV[2][16][EDIM];   // 16 KB
    __shared__ ull sMp[2][16][128];     // 32 KB  (total 48 KB)

    ull acc[8][4];
#pragma unroll
    for (int i = 0; i < 8; ++i)
#pragma unroll
        for (int j = 0; j < 4; ++j) acc[i][j] = 0ull;

    int nst = 16 * (tile + 1);

    int vs = tid >> 5, ve = (tid & 31) * 4;
    int ws = tid >> 6, wt = (tid & 63) * 2;

    float4 rv[2];
    ulonglong2 rw[4];

    auto load_stage = [&](int st) {
        int j0 = st * 16;
#pragma unroll
        for (int k = 0; k < 2; ++k) {
            int s = vs + k * 8;
            int j = j0 + s;
            int tau = j >> 1;
            const float* src = (j & 1) ? v2 : v1;
            rv[k] = *(const float4*)&src[((size_t)tau * BDIM + b) * EDIM + ve];
        }
#pragma unroll
        for (int k = 0; k < 4; ++k) {
            int s = ws + k * 4;
            rw[k] = *(const ulonglong2*)&g_mp[(size_t)(j0 + s) * TDIM + t0 + wt];
        }
    };
    auto store_stage = [&](int bf) {
#pragma unroll
        for (int k = 0; k < 2; ++k)
            *(float4*)&sV[bf][vs + k * 8][ve] = rv[k];
#pragma unroll
        for (int k = 0; k < 4; ++k)
            *(ulonglong2*)&sMp[bf][ws + k * 4][wt] = rw[k];
    };

    load_stage(0);
    for (int st = 0; st < nst; ++st) {
        int bf = st & 1;
        store_stage(bf);
        __syncthreads();
        if (st + 1 < nst) load_stage(st + 1);
#pragma unroll
        for (int s = 0; s < 16; ++s) {
            ulonglong2 vv0 = *(const ulonglong2*)&sV[bf][s][e0];
            ulonglong2 vv1 = *(const ulonglong2*)&sV[bf][s][e0 + 4];
            ull va0 = vv0.x, va1 = vv0.y, va2 = vv1.x, va3 = vv1.y;
#pragma unroll
            for (int h = 0; h < 4; ++h) {
                ulonglong2 wp = *(const ulonglong2*)&sMp[bf][s][r0 + 2 * h];
                acc[2 * h][0] = ffma2(wp.x, va0, acc[2 * h][0]);
                acc[2 * h][1] = ffma2(wp.x, va1, acc[2 * h][1]);
                acc[2 * h][2] = ffma2(wp.x, va2, acc[2 * h][2]);
                acc[2 * h][3] = ffma2(wp.x, va3, acc[2 * h][3]);
                acc[2 * h + 1][0] = ffma2(wp.y, va0, acc[2 * h + 1][0]);
                acc[2 * h + 1][1] = ffma2(wp.y, va1, acc[2 * h + 1][1]);
                acc[2 * h + 1][2] = ffma2(wp.y, va2, acc[2 * h + 1][2]);
                acc[2 * h + 1][3] = ffma2(wp.y, va3, acc[2 * h + 1][3]);
            }
        }
    }

    // write out [T][B][E]
#pragma unroll
    for (int i = 0; i < 8; ++i) {
        float r[8];
#pragma unroll
        for (int j = 0; j < 4; ++j) unpack2(acc[i][j], r[2 * j], r[2 * j + 1]);
        size_t basei = ((size_t)(t0 + r0 + i) * BDIM + b) * EDIM + e0;
        *reinterpret_cast<float4*>(out + basei) = make_float4(r[0], r[1], r[2], r[3]);
        *reinterpret_cast<float4*>(out + basei + 4) = make_float4(r[4], r[5], r[6], r[7]);
    }
}

// ---------------- K5: banded correction: out -= relu(m - s_b) * V -------
__global__ __launch_bounds__(256) void k_corr(const float* __restrict__ v1,
                                              const float* __restrict__ v2,
                                              float* __restrict__ out) {
    int t = blockIdx.x;
    int w = threadIdx.x >> 5, lane = threadIdx.x & 31;
    int js = g_js[t];
    if (js >= 2 * t + 2) return;
    int tau0 = js >> 1;

    for (int b = w; b < BDIM; b += 8) {
        const float* Pb = g_P + (size_t)b * PBSTRIDE;
        const float* t0b = g_t0T + (size_t)b * TDIM;
        const float* tpb = g_TPT + (size_t)b * TDIM;
        float4* op = (float4*)out + ((size_t)t * BDIM + b) * 32 + lane;
        float4 o = *op;
        bool touched = false;

        for (int tau = tau0; tau <= t; ++tau) {
            int n = t - tau;
            float R;
            if (n) {
                int k = 31 - __clz(n);
                R = fminf(Pb[k * TDIM + tau], Pb[k * TDIM + t - (1 << k)]);
            } else {
                R = INFV;
            }
            float Ca = fminf(t0b[tau], R);
            float Cp = fminf(tpb[tau], R);
            float Cm1 = tau ? fminf(tpb[tau - 1], fminf(Pb[tau - 1], R)) : 0.f;
            float s0 = Ca - Cm1;
            float s1 = Cp - Ca;
            float m0 = g_m[(size_t)(2 * tau) * TDIM + t];
            float m1 = g_m[(size_t)(2 * tau + 1) * TDIM + t];
            float c0 = fmaxf(m0 - s0, 0.f);
            float c1 = fmaxf(m1 - s1, 0.f);
            if (c0 > 0.f || c1 > 0.f) {
                size_t vb = ((size_t)tau * BDIM + b) * EDIM + lane * 4;
                float4 a = *(const float4*)(v1 + vb);
                float4 p = *(const float4*)(v2 + vb);
                o.x -= c0 * a.x + c1 * p.x;
                o.y -= c0 * a.y + c1 * p.y;
                o.z -= c0 * a.z + c1 * p.z;
                o.w -= c0 * a.w + c1 * p.w;
                touched = true;
            }
        }
        if (touched) *op = o;
    }
}

extern "C" void kernel_launch(void* const* d_in, const int* in_sizes, int n_in,
                              void* d_out, int out_size) {
    const float* v1 = (const float*)d_in[0];
    const float* v2 = (const float*)d_in[1];
    const float* d1 = (const float*)d_in[2];
    const float* d2 = (const float*)d_in[3];
    const float* u  = (const float*)d_in[4];
    float* out = (float*)d_out;

    k_A<<<NCH, 256>>>(d1, d2, u);         // 1
    k_B<<<BDIM, 256>>>(d1, d2, u);        // 2
    k_m<<<TDIM, 256>>>();                 // 3
    dim3 gm(BDIM, 4);
    k_gemm<<<gm, 256>>>(v1, v2, out);     // 4  <- ncu capture slot
    k_corr<<<TDIM, 256>>>(v1, v2, out);   // 5
}